// round 13
// baseline (speedup 1.0000x reference)
#include <cuda_runtime.h>
#include <cuda_bf16.h>
#include <cuda_fp16.h>
#include <mma.h>
#include <math.h>
#include <cstdint>

using namespace nvcuda;

#define D 128
#define MAX_N 100096
#define CAP 96
#define OVF_CAP 8192
#define BROWS 128
#define PK 64                   // K panel size

// Scratch (allocation-free rule: __device__ globals).
__device__ __half         g_Y[(size_t)MAX_N * D];    // Y = H * W' in fp16
__device__ float          g_c[D];                    // c = t.W + b
__device__ __nv_bfloat16  g_Whi[D * D];              // W' bf16 high part
__device__ __nv_bfloat16  g_Wlo[D * D];              // W' bf16 low part
__device__ int            g_cnt[MAX_N];              // per-node edge count
__device__ int2           g_edge[(size_t)MAX_N * CAP]; // buckets (src byte-off, w-bits)
__device__ int            g_ovf_cnt;                 // overflow list count
__device__ int4           g_ovf[OVF_CAP];            // overflow (dst, src byte-off, w, 0)

// ---------------------------------------------------------------------------
__global__ void zero_kernel(int n) {
    int i = blockIdx.x * blockDim.x + threadIdx.x;
    if (i < n) g_cnt[i] = 0;
    if (i == 0) g_ovf_cnt = 0;
}

// c[j] = bias[j] + sum_k (beta_k - mean_k*s_k) * W[k][j]
__global__ void prep_c_kernel(const float* __restrict__ W,
                              const float* __restrict__ bias,
                              const float* __restrict__ gamma,
                              const float* __restrict__ beta,
                              const float* __restrict__ mean,
                              const float* __restrict__ var) {
    int j = threadIdx.x;
    float acc = bias[j];
    for (int k = 0; k < D; k++) {
        float s = gamma[k] * rsqrtf(var[k] + 1e-3f);
        float t = beta[k] - mean[k] * s;
        acc += t * W[k * D + j];
    }
    g_c[j] = acc;
}

// Pre-split W' = diag(s)*W into bf16 hi/lo (done once; 782 gemm blocks copy).
__global__ void prep_w_kernel(const float* __restrict__ W,
                              const float* __restrict__ gamma,
                              const float* __restrict__ var) {
    int i = blockIdx.x * blockDim.x + threadIdx.x;   // 0..16383
    int k = i >> 7;
    float s = gamma[k] * rsqrtf(var[k] + 1e-3f);
    float v = W[i] * s;
    __nv_bfloat16 h = __float2bfloat16_rn(v);
    g_Whi[i] = h;
    g_Wlo[i] = __float2bfloat16_rn(v - __bfloat162float(h));
}

// ---------------------------------------------------------------------------
// Scatter: persistent 2 blocks/SM, 16 edges per thread-iteration (MLP~16).
// Buckets store the Y-row BYTE OFFSET (src*256).
// ---------------------------------------------------------------------------
__device__ __forceinline__ void scatter_one(int d, int s, float w) {
    int pos = atomicAdd(&g_cnt[d], 1);
    if (pos < CAP) {
        g_edge[(size_t)d * CAP + pos] = make_int2(s << 8, __float_as_int(w));
    } else {
        int slot = atomicAdd(&g_ovf_cnt, 1);
        if (slot < OVF_CAP)
            g_ovf[slot] = make_int4(d, s << 8, __float_as_int(w), 0);
    }
}

__device__ __forceinline__ void scatter_quad(const int4& s4, const int4& d4,
                                             const float4& w4) {
    scatter_one(d4.x, s4.x, w4.x);
    scatter_one(d4.y, s4.y, w4.y);
    scatter_one(d4.z, s4.z, w4.z);
    scatter_one(d4.w, s4.w, w4.w);
}

__global__ __launch_bounds__(256)
void scatter_kernel(const int*   __restrict__ src,
                    const int*   __restrict__ dst,
                    const float* __restrict__ ew,
                    int E) {
    int t      = blockIdx.x * blockDim.x + threadIdx.x;
    int stride = gridDim.x * blockDim.x;
    int nquad  = E >> 2;

    int q = t;
    for (; q + 3 * stride < nquad; q += 4 * stride) {
        int4   s0 = __ldg((const int4*)src + q);
        int4   s1 = __ldg((const int4*)src + q + stride);
        int4   s2 = __ldg((const int4*)src + q + 2 * stride);
        int4   s3 = __ldg((const int4*)src + q + 3 * stride);
        int4   d0 = __ldg((const int4*)dst + q);
        int4   d1 = __ldg((const int4*)dst + q + stride);
        int4   d2 = __ldg((const int4*)dst + q + 2 * stride);
        int4   d3 = __ldg((const int4*)dst + q + 3 * stride);
        float4 w0 = __ldg((const float4*)ew + q);
        float4 w1 = __ldg((const float4*)ew + q + stride);
        float4 w2 = __ldg((const float4*)ew + q + 2 * stride);
        float4 w3 = __ldg((const float4*)ew + q + 3 * stride);
        scatter_quad(s0, d0, w0);
        scatter_quad(s1, d1, w1);
        scatter_quad(s2, d2, w2);
        scatter_quad(s3, d3, w3);
    }
    for (; q < nquad; q += stride) {
        int4   s4 = __ldg((const int4*)src + q);
        int4   d4 = __ldg((const int4*)dst + q);
        float4 w4 = __ldg((const float4*)ew + q);
        scatter_quad(s4, d4, w4);
    }
    for (int i = nquad * 4 + t; i < E; i += stride)
        scatter_one(__ldg(dst + i), __ldg(src + i), __ldg(ew + i));
}

// ---------------------------------------------------------------------------
// GEMM: Y = H * W'   (bf16x3 tensor-core split), Y stored fp16.
// W panels arrive pre-split from prep_w: staging is straight uint4 copies.
// ---------------------------------------------------------------------------
#define LDA2 72
#define LDW2 136
#define LDWF 136

#define A_HI 0
#define A_LO (A_HI + BROWS * LDA2)
#define W_HI (A_LO + BROWS * LDA2)
#define W_LO (W_HI + PK * LDW2)
#define SMEM_BF (W_LO + PK * LDW2)        // 35840 bf16 = 71680 B

__global__ __launch_bounds__(256, 2)
void gemm_kernel(const float* __restrict__ H, int N) {
    extern __shared__ float smf[];
    __nv_bfloat16* smb = (__nv_bfloat16*)smf;

    int tid  = threadIdx.x;
    int row0 = blockIdx.x * BROWS;
    int wid  = tid >> 5;
    int m0   = (wid >> 1) * 32;
    int n0   = (wid & 1) * 64;

    wmma::fragment<wmma::accumulator, 16, 16, 16, float> acc[2][4];
    #pragma unroll
    for (int mf = 0; mf < 2; mf++)
        #pragma unroll
        for (int nf = 0; nf < 4; nf++) wmma::fill_fragment(acc[mf][nf], 0.0f);

    for (int p = 0; p < 2; p++) {
        int k0 = p * PK;

        // Stage A panel (bf16 hi/lo split of H): 128 rows x 64 k.
        #pragma unroll
        for (int t = 0; t < 8; t++) {
            int i  = tid + t * 256;
            int r  = i >> 4;
            int c4 = i & 15;
            int gr = row0 + r;
            float4 v = make_float4(0.f, 0.f, 0.f, 0.f);
            if (gr < N) v = __ldg((const float4*)(H + (size_t)gr * D) + (k0 >> 2) + c4);
            __nv_bfloat16 h0 = __float2bfloat16_rn(v.x);
            __nv_bfloat16 h1 = __float2bfloat16_rn(v.y);
            __nv_bfloat16 h2 = __float2bfloat16_rn(v.z);
            __nv_bfloat16 h3 = __float2bfloat16_rn(v.w);
            __nv_bfloat16 l0 = __float2bfloat16_rn(v.x - __bfloat162float(h0));
            __nv_bfloat16 l1 = __float2bfloat16_rn(v.y - __bfloat162float(h1));
            __nv_bfloat16 l2 = __float2bfloat16_rn(v.z - __bfloat162float(h2));
            __nv_bfloat16 l3 = __float2bfloat16_rn(v.w - __bfloat162float(h3));
            int o = r * LDA2 + c4 * 4;
            *(__nv_bfloat162*)(smb + A_HI + o)     = __halves2bfloat162(h0, h1);
            *(__nv_bfloat162*)(smb + A_HI + o + 2) = __halves2bfloat162(h2, h3);
            *(__nv_bfloat162*)(smb + A_LO + o)     = __halves2bfloat162(l0, l1);
            *(__nv_bfloat162*)(smb + A_LO + o + 2) = __halves2bfloat162(l2, l3);
        }

        // Stage W' panel: pure uint4 copies of pre-split bf16 (4/thread x2).
        #pragma unroll
        for (int t = 0; t < 4; t++) {
            int i  = tid + t * 256;          // 0..1023
            int k  = i >> 4;                 // 0..63  (16 uint4 per 128-col row)
            int c8 = i & 15;
            uint4 vh = __ldg((const uint4*)(g_Whi + (k0 + k) * D) + c8);
            uint4 vl = __ldg((const uint4*)(g_Wlo + (k0 + k) * D) + c8);
            int o = k * LDW2 + c8 * 8;
            *(uint4*)(smb + W_HI + o) = vh;
            *(uint4*)(smb + W_LO + o) = vl;
        }
        __syncthreads();

        #pragma unroll
        for (int kk = 0; kk < PK / 16; kk++) {
            wmma::fragment<wmma::matrix_a, 16, 16, 16, __nv_bfloat16, wmma::row_major> aHi[2], aLo[2];
            #pragma unroll
            for (int mf = 0; mf < 2; mf++) {
                wmma::load_matrix_sync(aHi[mf], smb + A_HI + (m0 + mf * 16) * LDA2 + kk * 16, LDA2);
                wmma::load_matrix_sync(aLo[mf], smb + A_LO + (m0 + mf * 16) * LDA2 + kk * 16, LDA2);
            }
            #pragma unroll
            for (int nf = 0; nf < 4; nf++) {
                wmma::fragment<wmma::matrix_b, 16, 16, 16, __nv_bfloat16, wmma::row_major> bHi, bLo;
                wmma::load_matrix_sync(bHi, smb + W_HI + kk * 16 * LDW2 + n0 + nf * 16, LDW2);
                wmma::load_matrix_sync(bLo, smb + W_LO + kk * 16 * LDW2 + n0 + nf * 16, LDW2);
                #pragma unroll
                for (int mf = 0; mf < 2; mf++) {
                    wmma::mma_sync(acc[mf][nf], aHi[mf], bHi, acc[mf][nf]);
                    wmma::mma_sync(acc[mf][nf], aHi[mf], bLo, acc[mf][nf]);
                    wmma::mma_sync(acc[mf][nf], aLo[mf], bHi, acc[mf][nf]);
                }
            }
        }
        __syncthreads();
    }

    #pragma unroll
    for (int mf = 0; mf < 2; mf++)
        #pragma unroll
        for (int nf = 0; nf < 4; nf++)
            wmma::store_matrix_sync(smf + (m0 + mf * 16) * LDWF + n0 + nf * 16,
                                    acc[mf][nf], LDWF, wmma::mem_row_major);
    __syncthreads();

    #pragma unroll
    for (int t = 0; t < 16; t++) {
        int i  = tid + t * 256;
        int r  = i >> 5;
        int c4 = i & 31;
        int gr = row0 + r;
        if (gr >= N) continue;
        const float* s = smf + r * LDWF + c4 * 4;
        __half2 p0 = __float22half2_rn(make_float2(s[0], s[1]));
        __half2 p1 = __float22half2_rn(make_float2(s[2], s[3]));
        uint2 u;
        u.x = *(unsigned int*)&p0;
        u.y = *(unsigned int*)&p1;
        *((uint2*)(g_Y + (size_t)gr * D) + c4) = u;
    }
}

// ---------------------------------------------------------------------------
// Gather: one warp per node; lane owns 4 columns; packed fma.rn.f32x2.
// ---------------------------------------------------------------------------
__device__ __forceinline__ float gelu_exact(float x) {
    return 0.5f * x * (1.0f + erff(x * 0.70710678118654752f));
}

__device__ __forceinline__ void acc_row(unsigned long long& a01,
                                        unsigned long long& a23,
                                        int byteoff, float w, int lane) {
    uint2 u = __ldg((const uint2*)((const char*)g_Y + byteoff) + lane);
    float2 f01 = __half22float2(*(const __half2*)&u.x);
    float2 f23 = __half22float2(*(const __half2*)&u.y);
    unsigned long long w2, y01, y23;
    asm("mov.b64 %0, {%1, %1};" : "=l"(w2)  : "f"(w));
    asm("mov.b64 %0, {%1, %2};" : "=l"(y01) : "f"(f01.x), "f"(f01.y));
    asm("mov.b64 %0, {%1, %2};" : "=l"(y23) : "f"(f23.x), "f"(f23.y));
    asm("fma.rn.f32x2 %0, %1, %2, %0;" : "+l"(a01) : "l"(y01), "l"(w2));
    asm("fma.rn.f32x2 %0, %1, %2, %0;" : "+l"(a23) : "l"(y23), "l"(w2));
}

__global__ __launch_bounds__(256)
void gather_kernel(float* __restrict__ out, int N) {
    int warp = (int)((blockIdx.x * (unsigned)blockDim.x + threadIdx.x) >> 5);
    int lane = threadIdx.x & 31;
    if (warp >= N) return;

    int cnt = g_cnt[warp];
    int deg = cnt < CAP ? cnt : CAP;
    const int2* lst = g_edge + (size_t)warp * CAP;

    unsigned long long a01 = 0ull, a23 = 0ull;

    int e = 0;
    for (; e + 4 <= deg; e += 4) {
        int4 a = __ldg((const int4*)(lst + e));
        int4 b = __ldg((const int4*)(lst + e) + 1);
        acc_row(a01, a23, a.x, __int_as_float(a.y), lane);
        acc_row(a01, a23, a.z, __int_as_float(a.w), lane);
        acc_row(a01, a23, b.x, __int_as_float(b.y), lane);
        acc_row(a01, a23, b.z, __int_as_float(b.w), lane);
    }
    for (; e < deg; e++) {
        int2 p = __ldg(lst + e);
        acc_row(a01, a23, p.x, __int_as_float(p.y), lane);
    }

    if (cnt > CAP) {   // merge rare overflow entries (Y complete by now)
        int m = g_ovf_cnt;
        if (m > OVF_CAP) m = OVF_CAP;
        for (int i = 0; i < m; i++) {
            int4 o = g_ovf[i];
            if (o.x == warp) acc_row(a01, a23, o.y, __int_as_float(o.z), lane);
        }
    }

    float ax, ay, az, aw;
    asm("mov.b64 {%0, %1}, %2;" : "=f"(ax), "=f"(ay) : "l"(a01));
    asm("mov.b64 {%0, %1}, %2;" : "=f"(az), "=f"(aw) : "l"(a23));

    float4 c4 = __ldg((const float4*)g_c + lane);
    float4 o;
    o.x = gelu_exact(ax + c4.x);
    o.y = gelu_exact(ay + c4.y);
    o.z = gelu_exact(az + c4.z);
    o.w = gelu_exact(aw + c4.w);
    *((float4*)(out + (size_t)warp * D) + lane) = o;
}

// ---------------------------------------------------------------------------
// Stream fork: persistent scatter (2 blocks/SM, side stream) co-resides with
// gemm (main stream) -- scatter leaves 1536 threads + 84KB smem per SM free.
// ---------------------------------------------------------------------------
static cudaStream_t s_side = 0;
static cudaEvent_t  s_e0 = 0, s_e1 = 0;

extern "C" void kernel_launch(void* const* d_in, const int* in_sizes, int n_in,
                              void* d_out, int out_size) {
    const float* H     = (const float*)d_in[0];
    const int*   src   = (const int*)  d_in[1];
    const int*   dst   = (const int*)  d_in[2];
    const float* ew    = (const float*)d_in[3];
    const float* gamma = (const float*)d_in[4];
    const float* beta  = (const float*)d_in[5];
    const float* mean  = (const float*)d_in[6];
    const float* var   = (const float*)d_in[7];
    const float* W     = (const float*)d_in[8];
    const float* bias  = (const float*)d_in[9];

    int N = in_sizes[0] / D;
    int E = in_sizes[1];

    if (s_side == 0) {
        cudaStreamCreateWithFlags(&s_side, cudaStreamNonBlocking);
        cudaEventCreateWithFlags(&s_e0, cudaEventDisableTiming);
        cudaEventCreateWithFlags(&s_e1, cudaEventDisableTiming);
    }

    zero_kernel<<<(N + 255) / 256, 256>>>(N);
    prep_c_kernel<<<1, D>>>(W, bias, gamma, beta, mean, var);
    prep_w_kernel<<<(D * D) / 256, 256>>>(W, gamma, var);

    // Fork: persistent scatter on side stream.
    cudaEventRecord(s_e0, 0);
    cudaStreamWaitEvent(s_side, s_e0, 0);
    scatter_kernel<<<296, 256, 0, s_side>>>(src, dst, ew, E);

    int smem_bytes = SMEM_BF * 2;            // 71680 B
    cudaFuncSetAttribute(gemm_kernel,
                         cudaFuncAttributeMaxDynamicSharedMemorySize, smem_bytes);
    gemm_kernel<<<(N + BROWS - 1) / BROWS, 256, smem_bytes>>>(H, N);

    // Join: gather needs both gemm (main) and scatter (side).
    cudaEventRecord(s_e1, s_side);
    cudaStreamWaitEvent(0, s_e1, 0);
    gather_kernel<<<(N * 32 + 255) / 256, 256>>>((float*)d_out, N);
}

// round 14
// speedup vs baseline: 1.1004x; 1.1004x over previous
#include <cuda_runtime.h>
#include <cuda_bf16.h>
#include <cuda_fp16.h>
#include <mma.h>
#include <math.h>
#include <cstdint>

using namespace nvcuda;

#define D 128
#define MAX_N 100096
#define CAP 96
#define OVF_CAP 8192
#define BROWS 128
#define PK 64                   // K panel size

// Scratch (allocation-free rule: __device__ globals).
__device__ __half         g_Y[(size_t)MAX_N * D];    // Y = H * W' in fp16
__device__ float          g_c[D];                    // c = t.W + b
__device__ __nv_bfloat16  g_Whi[D * D];              // W' bf16 high part
__device__ __nv_bfloat16  g_Wlo[D * D];              // W' bf16 low part
__device__ int            g_cnt[MAX_N];              // per-node edge count
__device__ int4           g_edge4[(size_t)MAX_N * (CAP / 2)];  // buckets, 16B-aligned
__device__ int            g_ovf_cnt;                 // overflow list count
__device__ int4           g_ovf[OVF_CAP];            // overflow (dst, src byte-off, w, 0)

// ---------------------------------------------------------------------------
__global__ void zero_kernel(int n) {
    int i = blockIdx.x * blockDim.x + threadIdx.x;
    if (i < n) g_cnt[i] = 0;
    if (i == 0) g_ovf_cnt = 0;
}

// Combined prep: blocks 0..63 split W' into bf16 hi/lo; block 64 computes c.
__global__ void prep_kernel(const float* __restrict__ W,
                            const float* __restrict__ bias,
                            const float* __restrict__ gamma,
                            const float* __restrict__ beta,
                            const float* __restrict__ mean,
                            const float* __restrict__ var) {
    int tid = threadIdx.x;
    if (blockIdx.x < 64) {
        int i = blockIdx.x * 256 + tid;      // 0..16383
        int k = i >> 7;
        float s = gamma[k] * rsqrtf(var[k] + 1e-3f);
        float v = W[i] * s;
        __nv_bfloat16 h = __float2bfloat16_rn(v);
        g_Whi[i] = h;
        g_Wlo[i] = __float2bfloat16_rn(v - __bfloat162float(h));
    } else if (tid < D) {
        float acc = bias[tid];
        for (int k = 0; k < D; k++) {
            float s = gamma[k] * rsqrtf(var[k] + 1e-3f);
            float t = beta[k] - mean[k] * s;
            acc += t * W[k * D + tid];
        }
        g_c[tid] = acc;
    }
}

// ---------------------------------------------------------------------------
// Scatter: 8 edges per thread (MLP~8 on the atomics), high-occupancy grid.
// Buckets store the Y-row BYTE OFFSET (src*256).
// ---------------------------------------------------------------------------
__device__ __forceinline__ void scatter_one(int d, int s, float w) {
    int pos = atomicAdd(&g_cnt[d], 1);
    if (pos < CAP) {
        ((int2*)g_edge4)[(size_t)d * CAP + pos] = make_int2(s << 8, __float_as_int(w));
    } else {
        int slot = atomicAdd(&g_ovf_cnt, 1);
        if (slot < OVF_CAP)
            g_ovf[slot] = make_int4(d, s << 8, __float_as_int(w), 0);
    }
}

__device__ __forceinline__ void scatter_quad(const int4& s4, const int4& d4,
                                             const float4& w4) {
    scatter_one(d4.x, s4.x, w4.x);
    scatter_one(d4.y, s4.y, w4.y);
    scatter_one(d4.z, s4.z, w4.z);
    scatter_one(d4.w, s4.w, w4.w);
}

__global__ __launch_bounds__(256)
void scatter_kernel(const int*   __restrict__ src,
                    const int*   __restrict__ dst,
                    const float* __restrict__ ew,
                    int E) {
    int t  = blockIdx.x * blockDim.x + threadIdx.x;
    int i0 = t * 8;
    if (i0 + 7 < E) {
        int4   sa = __ldg((const int4*)(src + i0));
        int4   sb = __ldg((const int4*)(src + i0) + 1);
        int4   da = __ldg((const int4*)(dst + i0));
        int4   db = __ldg((const int4*)(dst + i0) + 1);
        float4 wa = __ldg((const float4*)(ew + i0));
        float4 wb = __ldg((const float4*)(ew + i0) + 1);
        scatter_quad(sa, da, wa);
        scatter_quad(sb, db, wb);
    } else {
        for (int i = i0; i < E; i++)
            scatter_one(__ldg(dst + i), __ldg(src + i), __ldg(ew + i));
    }
}

// ---------------------------------------------------------------------------
// GEMM: Y = H * W'   (bf16x3 tensor-core split), Y stored fp16.
// W panels pre-split by prep_kernel: staging is straight uint4 copies.
// ---------------------------------------------------------------------------
#define LDA2 72
#define LDW2 136
#define LDWF 136

#define A_HI 0
#define A_LO (A_HI + BROWS * LDA2)
#define W_HI (A_LO + BROWS * LDA2)
#define W_LO (W_HI + PK * LDW2)
#define SMEM_BF (W_LO + PK * LDW2)        // 35840 bf16 = 71680 B

__global__ __launch_bounds__(256, 2)
void gemm_kernel(const float* __restrict__ H, int N) {
    extern __shared__ float smf[];
    __nv_bfloat16* smb = (__nv_bfloat16*)smf;

    int tid  = threadIdx.x;
    int row0 = blockIdx.x * BROWS;
    int wid  = tid >> 5;
    int m0   = (wid >> 1) * 32;
    int n0   = (wid & 1) * 64;

    wmma::fragment<wmma::accumulator, 16, 16, 16, float> acc[2][4];
    #pragma unroll
    for (int mf = 0; mf < 2; mf++)
        #pragma unroll
        for (int nf = 0; nf < 4; nf++) wmma::fill_fragment(acc[mf][nf], 0.0f);

    for (int p = 0; p < 2; p++) {
        int k0 = p * PK;

        // Stage A panel (bf16 hi/lo split of H): 128 rows x 64 k.
        #pragma unroll
        for (int t = 0; t < 8; t++) {
            int i  = tid + t * 256;
            int r  = i >> 4;
            int c4 = i & 15;
            int gr = row0 + r;
            float4 v = make_float4(0.f, 0.f, 0.f, 0.f);
            if (gr < N) v = __ldg((const float4*)(H + (size_t)gr * D) + (k0 >> 2) + c4);
            __nv_bfloat16 h0 = __float2bfloat16_rn(v.x);
            __nv_bfloat16 h1 = __float2bfloat16_rn(v.y);
            __nv_bfloat16 h2 = __float2bfloat16_rn(v.z);
            __nv_bfloat16 h3 = __float2bfloat16_rn(v.w);
            __nv_bfloat16 l0 = __float2bfloat16_rn(v.x - __bfloat162float(h0));
            __nv_bfloat16 l1 = __float2bfloat16_rn(v.y - __bfloat162float(h1));
            __nv_bfloat16 l2 = __float2bfloat16_rn(v.z - __bfloat162float(h2));
            __nv_bfloat16 l3 = __float2bfloat16_rn(v.w - __bfloat162float(h3));
            int o = r * LDA2 + c4 * 4;
            *(__nv_bfloat162*)(smb + A_HI + o)     = __halves2bfloat162(h0, h1);
            *(__nv_bfloat162*)(smb + A_HI + o + 2) = __halves2bfloat162(h2, h3);
            *(__nv_bfloat162*)(smb + A_LO + o)     = __halves2bfloat162(l0, l1);
            *(__nv_bfloat162*)(smb + A_LO + o + 2) = __halves2bfloat162(l2, l3);
        }

        // Stage W' panel: pure uint4 copies of pre-split bf16.
        #pragma unroll
        for (int t = 0; t < 4; t++) {
            int i  = tid + t * 256;          // 0..1023
            int k  = i >> 4;                 // 0..63  (16 uint4 per 128-col row)
            int c8 = i & 15;
            uint4 vh = __ldg((const uint4*)(g_Whi + (k0 + k) * D) + c8);
            uint4 vl = __ldg((const uint4*)(g_Wlo + (k0 + k) * D) + c8);
            int o = k * LDW2 + c8 * 8;
            *(uint4*)(smb + W_HI + o) = vh;
            *(uint4*)(smb + W_LO + o) = vl;
        }
        __syncthreads();

        #pragma unroll
        for (int kk = 0; kk < PK / 16; kk++) {
            wmma::fragment<wmma::matrix_a, 16, 16, 16, __nv_bfloat16, wmma::row_major> aHi[2], aLo[2];
            #pragma unroll
            for (int mf = 0; mf < 2; mf++) {
                wmma::load_matrix_sync(aHi[mf], smb + A_HI + (m0 + mf * 16) * LDA2 + kk * 16, LDA2);
                wmma::load_matrix_sync(aLo[mf], smb + A_LO + (m0 + mf * 16) * LDA2 + kk * 16, LDA2);
            }
            #pragma unroll
            for (int nf = 0; nf < 4; nf++) {
                wmma::fragment<wmma::matrix_b, 16, 16, 16, __nv_bfloat16, wmma::row_major> bHi, bLo;
                wmma::load_matrix_sync(bHi, smb + W_HI + kk * 16 * LDW2 + n0 + nf * 16, LDW2);
                wmma::load_matrix_sync(bLo, smb + W_LO + kk * 16 * LDW2 + n0 + nf * 16, LDW2);
                #pragma unroll
                for (int mf = 0; mf < 2; mf++) {
                    wmma::mma_sync(acc[mf][nf], aHi[mf], bHi, acc[mf][nf]);
                    wmma::mma_sync(acc[mf][nf], aHi[mf], bLo, acc[mf][nf]);
                    wmma::mma_sync(acc[mf][nf], aLo[mf], bHi, acc[mf][nf]);
                }
            }
        }
        __syncthreads();
    }

    #pragma unroll
    for (int mf = 0; mf < 2; mf++)
        #pragma unroll
        for (int nf = 0; nf < 4; nf++)
            wmma::store_matrix_sync(smf + (m0 + mf * 16) * LDWF + n0 + nf * 16,
                                    acc[mf][nf], LDWF, wmma::mem_row_major);
    __syncthreads();

    #pragma unroll
    for (int t = 0; t < 16; t++) {
        int i  = tid + t * 256;
        int r  = i >> 5;
        int c4 = i & 31;
        int gr = row0 + r;
        if (gr >= N) continue;
        const float* s = smf + r * LDWF + c4 * 4;
        __half2 p0 = __float22half2_rn(make_float2(s[0], s[1]));
        __half2 p1 = __float22half2_rn(make_float2(s[2], s[3]));
        uint2 u;
        u.x = *(unsigned int*)&p0;
        u.y = *(unsigned int*)&p1;
        *((uint2*)(g_Y + (size_t)gr * D) + c4) = u;
    }
}

// ---------------------------------------------------------------------------
// Gather: one warp per node; lane owns 4 columns.  8-edge unroll: all 8
// Y-row loads issued before the FMA chains (MLP~8).
// ---------------------------------------------------------------------------
__device__ __forceinline__ float gelu_exact(float x) {
    return 0.5f * x * (1.0f + erff(x * 0.70710678118654752f));
}

__device__ __forceinline__ void fmaacc(float4& a, uint2 u, float w) {
    float2 f01 = __half22float2(*(const __half2*)&u.x);
    float2 f23 = __half22float2(*(const __half2*)&u.y);
    a.x += w * f01.x; a.y += w * f01.y;
    a.z += w * f23.x; a.w += w * f23.y;
}

__global__ __launch_bounds__(256)
void gather_kernel(float* __restrict__ out, int N) {
    int warp = (int)((blockIdx.x * (unsigned)blockDim.x + threadIdx.x) >> 5);
    int lane = threadIdx.x & 31;
    if (warp >= N) return;

    int cnt = g_cnt[warp];
    int deg = cnt < CAP ? cnt : CAP;
    const int4* lst4 = g_edge4 + (size_t)warp * (CAP / 2);

    float4 acc = make_float4(0.f, 0.f, 0.f, 0.f);

    int e = 0;
    for (; e + 8 <= deg; e += 8) {
        int4 m0 = __ldg(lst4 + (e >> 1));
        int4 m1 = __ldg(lst4 + (e >> 1) + 1);
        int4 m2 = __ldg(lst4 + (e >> 1) + 2);
        int4 m3 = __ldg(lst4 + (e >> 1) + 3);
        uint2 u0 = __ldg((const uint2*)((const char*)g_Y + m0.x) + lane);
        uint2 u1 = __ldg((const uint2*)((const char*)g_Y + m0.z) + lane);
        uint2 u2 = __ldg((const uint2*)((const char*)g_Y + m1.x) + lane);
        uint2 u3 = __ldg((const uint2*)((const char*)g_Y + m1.z) + lane);
        uint2 u4 = __ldg((const uint2*)((const char*)g_Y + m2.x) + lane);
        uint2 u5 = __ldg((const uint2*)((const char*)g_Y + m2.z) + lane);
        uint2 u6 = __ldg((const uint2*)((const char*)g_Y + m3.x) + lane);
        uint2 u7 = __ldg((const uint2*)((const char*)g_Y + m3.z) + lane);
        fmaacc(acc, u0, __int_as_float(m0.y));
        fmaacc(acc, u1, __int_as_float(m0.w));
        fmaacc(acc, u2, __int_as_float(m1.y));
        fmaacc(acc, u3, __int_as_float(m1.w));
        fmaacc(acc, u4, __int_as_float(m2.y));
        fmaacc(acc, u5, __int_as_float(m2.w));
        fmaacc(acc, u6, __int_as_float(m3.y));
        fmaacc(acc, u7, __int_as_float(m3.w));
    }
    for (; e < deg; e++) {
        int2 p = __ldg((const int2*)lst4 + e);
        uint2 u = __ldg((const uint2*)((const char*)g_Y + p.x) + lane);
        fmaacc(acc, u, __int_as_float(p.y));
    }

    if (cnt > CAP) {   // merge rare overflow entries (Y complete by now)
        int m = g_ovf_cnt;
        if (m > OVF_CAP) m = OVF_CAP;
        for (int i = 0; i < m; i++) {
            int4 o = g_ovf[i];
            if (o.x == warp) {
                uint2 u = __ldg((const uint2*)((const char*)g_Y + o.y) + lane);
                fmaacc(acc, u, __int_as_float(o.z));
            }
        }
    }

    float4 c4 = __ldg((const float4*)g_c + lane);
    float4 o;
    o.x = gelu_exact(acc.x + c4.x);
    o.y = gelu_exact(acc.y + c4.y);
    o.z = gelu_exact(acc.z + c4.z);
    o.w = gelu_exact(acc.w + c4.w);
    *((float4*)(out + (size_t)warp * D) + lane) = o;
}

// ---------------------------------------------------------------------------
static cudaStream_t s_side = 0;
static cudaEvent_t  s_e0 = 0, s_e1 = 0;

extern "C" void kernel_launch(void* const* d_in, const int* in_sizes, int n_in,
                              void* d_out, int out_size) {
    const float* H     = (const float*)d_in[0];
    const int*   src   = (const int*)  d_in[1];
    const int*   dst   = (const int*)  d_in[2];
    const float* ew    = (const float*)d_in[3];
    const float* gamma = (const float*)d_in[4];
    const float* beta  = (const float*)d_in[5];
    const float* mean  = (const float*)d_in[6];
    const float* var   = (const float*)d_in[7];
    const float* W     = (const float*)d_in[8];
    const float* bias  = (const float*)d_in[9];

    int N = in_sizes[0] / D;
    int E = in_sizes[1];

    if (s_side == 0) {
        cudaStreamCreateWithFlags(&s_side, cudaStreamNonBlocking);
        cudaEventCreateWithFlags(&s_e0, cudaEventDisableTiming);
        cudaEventCreateWithFlags(&s_e1, cudaEventDisableTiming);
    }

    zero_kernel<<<(N + 255) / 256, 256>>>(N);
    prep_kernel<<<65, 256>>>(W, bias, gamma, beta, mean, var);

    // Fork: scatter on side stream (kept; costs nothing even if serial).
    cudaEventRecord(s_e0, 0);
    cudaStreamWaitEvent(s_side, s_e0, 0);
    int sblocks = (E / 8 + 255) / 256 + 1;
    scatter_kernel<<<sblocks, 256, 0, s_side>>>(src, dst, ew, E);

    int smem_bytes = SMEM_BF * 2;            // 71680 B
    cudaFuncSetAttribute(gemm_kernel,
                         cudaFuncAttributeMaxDynamicSharedMemorySize, smem_bytes);
    gemm_kernel<<<(N + BROWS - 1) / BROWS, 256, smem_bytes>>>(H, N);

    // Join: gather needs both gemm (main) and scatter (side).
    cudaEventRecord(s_e1, s_side);
    cudaStreamWaitEvent(0, s_e1, 0);
    gather_kernel<<<(N * 32 + 255) / 256, 256>>>((float*)d_out, N);
}

// round 16
// speedup vs baseline: 1.2197x; 1.1084x over previous
#include <cuda_runtime.h>
#include <cuda_fp16.h>
#include <mma.h>
#include <math.h>
#include <cstdint>

using namespace nvcuda;

#define D 128
#define MAX_N 100096
#define CAP 96
#define OVF_CAP 8192
#define BROWS 128
#define PK 64                   // K panel size

// Scratch (allocation-free rule: __device__ globals).
__device__ __half  g_Y[(size_t)MAX_N * D];      // Y = H * W' in fp16
__device__ float   g_c[D];                      // c = t.W + b
__device__ __half  g_Wh[D * D];                 // W' fp16  [k][n]
__device__ int     g_cnt[MAX_N];                // per-node edge count
__device__ int4    g_edge4[(size_t)MAX_N * (CAP / 2)];  // buckets, 16B-aligned
__device__ int     g_ovf_cnt;                   // overflow list count
__device__ int4    g_ovf[OVF_CAP];              // overflow (dst, src byte-off, w, 0)

// ---------------------------------------------------------------------------
__global__ void zero_kernel(int n) {
    int i = blockIdx.x * blockDim.x + threadIdx.x;
    if (i < n) g_cnt[i] = 0;
    if (i == 0) g_ovf_cnt = 0;
}

// Combined prep: blocks 0..63 convert W' to fp16; block 64 computes c.
__global__ void prep_kernel(const float* __restrict__ W,
                            const float* __restrict__ bias,
                            const float* __restrict__ gamma,
                            const float* __restrict__ beta,
                            const float* __restrict__ mean,
                            const float* __restrict__ var) {
    int tid = threadIdx.x;
    if (blockIdx.x < 64) {
        int i = blockIdx.x * 256 + tid;      // 0..16383 = k*128 + n
        int k = i >> 7;
        float s = gamma[k] * rsqrtf(var[k] + 1e-3f);
        g_Wh[i] = __float2half_rn(W[i] * s);
    } else if (tid < D) {
        float acc = bias[tid];
        for (int k = 0; k < D; k++) {
            float s = gamma[k] * rsqrtf(var[k] + 1e-3f);
            float t = beta[k] - mean[k] * s;
            acc += t * W[k * D + tid];
        }
        g_c[tid] = acc;
    }
}

// ---------------------------------------------------------------------------
// Scatter: 8 edges per thread (MLP~8 on the atomics).
// Buckets store the Y-row BYTE OFFSET (src*256).
// ---------------------------------------------------------------------------
__device__ __forceinline__ void scatter_one(int d, int s, float w) {
    int pos = atomicAdd(&g_cnt[d], 1);
    if (pos < CAP) {
        ((int2*)g_edge4)[(size_t)d * CAP + pos] = make_int2(s << 8, __float_as_int(w));
    } else {
        int slot = atomicAdd(&g_ovf_cnt, 1);
        if (slot < OVF_CAP)
            g_ovf[slot] = make_int4(d, s << 8, __float_as_int(w), 0);
    }
}

__device__ __forceinline__ void scatter_quad(const int4& s4, const int4& d4,
                                             const float4& w4) {
    scatter_one(d4.x, s4.x, w4.x);
    scatter_one(d4.y, s4.y, w4.y);
    scatter_one(d4.z, s4.z, w4.z);
    scatter_one(d4.w, s4.w, w4.w);
}

__global__ __launch_bounds__(256)
void scatter_kernel(const int*   __restrict__ src,
                    const int*   __restrict__ dst,
                    const float* __restrict__ ew,
                    int E) {
    int t  = blockIdx.x * blockDim.x + threadIdx.x;
    int i0 = t * 8;
    if (i0 + 7 < E) {
        int4   sa = __ldg((const int4*)(src + i0));
        int4   sb = __ldg((const int4*)(src + i0) + 1);
        int4   da = __ldg((const int4*)(dst + i0));
        int4   db = __ldg((const int4*)(dst + i0) + 1);
        float4 wa = __ldg((const float4*)(ew + i0));
        float4 wb = __ldg((const float4*)(ew + i0) + 1);
        scatter_quad(sa, da, wa);
        scatter_quad(sb, db, wb);
    } else {
        for (int i = i0; i < E; i++)
            scatter_one(__ldg(dst + i), __ldg(src + i), __ldg(ew + i));
    }
}

// ---------------------------------------------------------------------------
// GEMM: Y = H * W'  (single-term fp16 tensor-core, fp32 accumulate).
// 128x128 tile/CTA, 256 threads / 8 warps (warp = 32m x 64n), K in 2 panels.
// Error floor ~2^-11, matched to the fp16 Y storage quantization.
// ---------------------------------------------------------------------------
#define LDA2 72     // fp16 elems per A panel row  (64 + 8 pad)
#define LDW2 136    // fp16 elems per W panel row  (128 + 8 pad)
#define LDWF 136    // fp32 epilogue tile leading dim

#define A_OFF 0
#define W_OFF (A_OFF + BROWS * LDA2)      // 9216

__global__ __launch_bounds__(256, 2)
void gemm_kernel(const float* __restrict__ H, int N) {
    extern __shared__ float smf[];
    __half* smh = (__half*)smf;

    int tid  = threadIdx.x;
    int row0 = blockIdx.x * BROWS;
    int wid  = tid >> 5;
    int m0   = (wid >> 1) * 32;
    int n0   = (wid & 1) * 64;

    wmma::fragment<wmma::accumulator, 16, 16, 16, float> acc[2][4];
    #pragma unroll
    for (int mf = 0; mf < 2; mf++)
        #pragma unroll
        for (int nf = 0; nf < 4; nf++) wmma::fill_fragment(acc[mf][nf], 0.0f);

    for (int p = 0; p < 2; p++) {
        int k0 = p * PK;

        // Stage A panel (fp16 cvt of H): 128 rows x 64 k, 8 float4/thread.
        #pragma unroll
        for (int t = 0; t < 8; t++) {
            int i  = tid + t * 256;          // 0..2047
            int r  = i >> 4;                 // row 0..127  (16 float4/row)
            int c4 = i & 15;
            int gr = row0 + r;
            float4 v = make_float4(0.f, 0.f, 0.f, 0.f);
            if (gr < N) v = __ldg((const float4*)(H + (size_t)gr * D) + (k0 >> 2) + c4);
            __half2 p0 = __float22half2_rn(make_float2(v.x, v.y));
            __half2 p1 = __float22half2_rn(make_float2(v.z, v.w));
            int o = r * LDA2 + c4 * 4;
            *(__half2*)(smh + A_OFF + o)     = p0;
            *(__half2*)(smh + A_OFF + o + 2) = p1;
        }

        // Stage W' panel: pure uint4 copies of pre-converted fp16 (4/thread).
        #pragma unroll
        for (int t = 0; t < 4; t++) {
            int i  = tid + t * 256;          // 0..1023
            int k  = i >> 4;                 // 0..63  (16 uint4 per 128-col row)
            int c8 = i & 15;
            uint4 vh = __ldg((const uint4*)(g_Wh + (k0 + k) * D) + c8);
            *(uint4*)(smh + W_OFF + k * LDW2 + c8 * 8) = vh;
        }
        __syncthreads();

        #pragma unroll
        for (int kk = 0; kk < PK / 16; kk++) {
            wmma::fragment<wmma::matrix_a, 16, 16, 16, __half, wmma::row_major> a[2];
            #pragma unroll
            for (int mf = 0; mf < 2; mf++)
                wmma::load_matrix_sync(a[mf], smh + A_OFF + (m0 + mf * 16) * LDA2 + kk * 16, LDA2);
            #pragma unroll
            for (int nf = 0; nf < 4; nf++) {
                wmma::fragment<wmma::matrix_b, 16, 16, 16, __half, wmma::row_major> b;
                wmma::load_matrix_sync(b, smh + W_OFF + kk * 16 * LDW2 + n0 + nf * 16, LDW2);
                #pragma unroll
                for (int mf = 0; mf < 2; mf++)
                    wmma::mma_sync(acc[mf][nf], a[mf], b, acc[mf][nf]);
            }
        }
        __syncthreads();
    }

    // Epilogue: dump accs to fp32 smem tile, convert to fp16 Y, store.
    #pragma unroll
    for (int mf = 0; mf < 2; mf++)
        #pragma unroll
        for (int nf = 0; nf < 4; nf++)
            wmma::store_matrix_sync(smf + (m0 + mf * 16) * LDWF + n0 + nf * 16,
                                    acc[mf][nf], LDWF, wmma::mem_row_major);
    __syncthreads();

    #pragma unroll
    for (int t = 0; t < 16; t++) {
        int i  = tid + t * 256;              // 0..4095  (128 rows x 32 groups)
        int r  = i >> 5;
        int c4 = i & 31;
        int gr = row0 + r;
        if (gr >= N) continue;
        const float* s = smf + r * LDWF + c4 * 4;
        __half2 p0 = __float22half2_rn(make_float2(s[0], s[1]));
        __half2 p1 = __float22half2_rn(make_float2(s[2], s[3]));
        uint2 u;
        u.x = *(unsigned int*)&p0;
        u.y = *(unsigned int*)&p1;
        *((uint2*)(g_Y + (size_t)gr * D) + c4) = u;
    }
}

// ---------------------------------------------------------------------------
// Gather: one warp per node; lane owns 4 columns.  8-edge unroll (MLP~8).
// ---------------------------------------------------------------------------
__device__ __forceinline__ float gelu_exact(float x) {
    return 0.5f * x * (1.0f + erff(x * 0.70710678118654752f));
}

__device__ __forceinline__ void fmaacc(float4& a, uint2 u, float w) {
    float2 f01 = __half22float2(*(const __half2*)&u.x);
    float2 f23 = __half22float2(*(const __half2*)&u.y);
    a.x += w * f01.x; a.y += w * f01.y;
    a.z += w * f23.x; a.w += w * f23.y;
}

__global__ __launch_bounds__(256)
void gather_kernel(float* __restrict__ out, int N) {
    int warp = (int)((blockIdx.x * (unsigned)blockDim.x + threadIdx.x) >> 5);
    int lane = threadIdx.x & 31;
    if (warp >= N) return;

    int cnt = g_cnt[warp];
    int deg = cnt < CAP ? cnt : CAP;
    const int4* lst4 = g_edge4 + (size_t)warp * (CAP / 2);

    float4 acc = make_float4(0.f, 0.f, 0.f, 0.f);

    int e = 0;
    for (; e + 8 <= deg; e += 8) {
        int4 m0 = __ldg(lst4 + (e >> 1));
        int4 m1 = __ldg(lst4 + (e >> 1) + 1);
        int4 m2 = __ldg(lst4 + (e >> 1) + 2);
        int4 m3 = __ldg(lst4 + (e >> 1) + 3);
        uint2 u0 = __ldg((const uint2*)((const char*)g_Y + m0.x) + lane);
        uint2 u1 = __ldg((const uint2*)((const char*)g_Y + m0.z) + lane);
        uint2 u2 = __ldg((const uint2*)((const char*)g_Y + m1.x) + lane);
        uint2 u3 = __ldg((const uint2*)((const char*)g_Y + m1.z) + lane);
        uint2 u4 = __ldg((const uint2*)((const char*)g_Y + m2.x) + lane);
        uint2 u5 = __ldg((const uint2*)((const char*)g_Y + m2.z) + lane);
        uint2 u6 = __ldg((const uint2*)((const char*)g_Y + m3.x) + lane);
        uint2 u7 = __ldg((const uint2*)((const char*)g_Y + m3.z) + lane);
        fmaacc(acc, u0, __int_as_float(m0.y));
        fmaacc(acc, u1, __int_as_float(m0.w));
        fmaacc(acc, u2, __int_as_float(m1.y));
        fmaacc(acc, u3, __int_as_float(m1.w));
        fmaacc(acc, u4, __int_as_float(m2.y));
        fmaacc(acc, u5, __int_as_float(m2.w));
        fmaacc(acc, u6, __int_as_float(m3.y));
        fmaacc(acc, u7, __int_as_float(m3.w));
    }
    for (; e < deg; e++) {
        int2 p = __ldg((const int2*)lst4 + e);
        uint2 u = __ldg((const uint2*)((const char*)g_Y + p.x) + lane);
        fmaacc(acc, u, __int_as_float(p.y));
    }

    if (cnt > CAP) {   // merge rare overflow entries (Y complete by now)
        int m = g_ovf_cnt;
        if (m > OVF_CAP) m = OVF_CAP;
        for (int i = 0; i < m; i++) {
            int4 o = g_ovf[i];
            if (o.x == warp) {
                uint2 u = __ldg((const uint2*)((const char*)g_Y + o.y) + lane);
                fmaacc(acc, u, __int_as_float(o.z));
            }
        }
    }

    float4 c4 = __ldg((const float4*)g_c + lane);
    float4 o;
    o.x = gelu_exact(acc.x + c4.x);
    o.y = gelu_exact(acc.y + c4.y);
    o.z = gelu_exact(acc.z + c4.z);
    o.w = gelu_exact(acc.w + c4.w);
    *((float4*)(out + (size_t)warp * D) + lane) = o;
}

// ---------------------------------------------------------------------------
static cudaStream_t s_side = 0;
static cudaEvent_t  s_e0 = 0, s_e1 = 0;

extern "C" void kernel_launch(void* const* d_in, const int* in_sizes, int n_in,
                              void* d_out, int out_size) {
    const float* H     = (const float*)d_in[0];
    const int*   src   = (const int*)  d_in[1];
    const int*   dst   = (const int*)  d_in[2];
    const float* ew    = (const float*)d_in[3];
    const float* gamma = (const float*)d_in[4];
    const float* beta  = (const float*)d_in[5];
    const float* mean  = (const float*)d_in[6];
    const float* var   = (const float*)d_in[7];
    const float* W     = (const float*)d_in[8];
    const float* bias  = (const float*)d_in[9];

    int N = in_sizes[0] / D;
    int E = in_sizes[1];

    if (s_side == 0) {
        cudaStreamCreateWithFlags(&s_side, cudaStreamNonBlocking);
        cudaEventCreateWithFlags(&s_e0, cudaEventDisableTiming);
        cudaEventCreateWithFlags(&s_e1, cudaEventDisableTiming);
    }

    zero_kernel<<<(N + 255) / 256, 256>>>(N);
    prep_kernel<<<65, 256>>>(W, bias, gamma, beta, mean, var);

    // Fork: scatter on side stream.
    cudaEventRecord(s_e0, 0);
    cudaStreamWaitEvent(s_side, s_e0, 0);
    int sblocks = (E / 8 + 255) / 256 + 1;
    scatter_kernel<<<sblocks, 256, 0, s_side>>>(src, dst, ew, E);

    int smem_bytes = BROWS * LDWF * 4;       // 69632 B (epilogue fp32 tile)
    cudaFuncSetAttribute(gemm_kernel,
                         cudaFuncAttributeMaxDynamicSharedMemorySize, smem_bytes);
    gemm_kernel<<<(N + BROWS - 1) / BROWS, 256, smem_bytes>>>(H, N);

    // Join: gather needs both gemm (main) and scatter (side).
    cudaEventRecord(s_e1, s_side);
    cudaStreamWaitEvent(0, s_e1, 0);
    gather_kernel<<<(N * 32 + 255) / 256, 256>>>((float*)d_out, N);
}

// round 17
// speedup vs baseline: 1.2199x; 1.0002x over previous
#include <cuda_runtime.h>
#include <cuda_fp16.h>
#include <mma.h>
#include <math.h>
#include <cstdint>

using namespace nvcuda;

#define D 128
#define MAX_N 100096
#define CAP 96
#define OVF_CAP 8192
#define BROWS 128

// Scratch (allocation-free rule: __device__ globals).
__device__ __half  g_Y[(size_t)MAX_N * D];      // Y = H * W' in fp16
__device__ float   g_c[D];                      // c = t.W + b
__device__ __half  g_Wh[D * D];                 // W' fp16  [k][n]
__device__ int     g_cnt[MAX_N];                // per-node edge count
__device__ int4    g_edge4[(size_t)MAX_N * (CAP / 2)];  // buckets, 16B-aligned
__device__ int     g_ovf_cnt;                   // overflow list count
__device__ int4    g_ovf[OVF_CAP];              // overflow (dst, src byte-off, w, 0)

// ---------------------------------------------------------------------------
// Combined init: blocks 0..390 zero counters; 391..454 convert W'; 455 does c.
// ---------------------------------------------------------------------------
__global__ void prep_all_kernel(const float* __restrict__ W,
                                const float* __restrict__ bias,
                                const float* __restrict__ gamma,
                                const float* __restrict__ beta,
                                const float* __restrict__ mean,
                                const float* __restrict__ var,
                                int n) {
    int b   = blockIdx.x;
    int tid = threadIdx.x;
    if (b < 391) {
        int i = b * 256 + tid;
        if (i < n) g_cnt[i] = 0;
        if (i == 0) g_ovf_cnt = 0;
    } else if (b < 455) {
        int i = (b - 391) * 256 + tid;       // 0..16383 = k*128 + n
        int k = i >> 7;
        float s = gamma[k] * rsqrtf(var[k] + 1e-3f);
        g_Wh[i] = __float2half_rn(W[i] * s);
    } else if (tid < D) {
        float acc = bias[tid];
        for (int k = 0; k < D; k++) {
            float s = gamma[k] * rsqrtf(var[k] + 1e-3f);
            float t = beta[k] - mean[k] * s;
            acc += t * W[k * D + tid];
        }
        g_c[tid] = acc;
    }
}

// ---------------------------------------------------------------------------
// Scatter: 8 edges per thread (MLP~8 on the atomics).
// Buckets store the Y-row BYTE OFFSET (src*256).
// ---------------------------------------------------------------------------
__device__ __forceinline__ void scatter_one(int d, int s, float w) {
    int pos = atomicAdd(&g_cnt[d], 1);
    if (pos < CAP) {
        ((int2*)g_edge4)[(size_t)d * CAP + pos] = make_int2(s << 8, __float_as_int(w));
    } else {
        int slot = atomicAdd(&g_ovf_cnt, 1);
        if (slot < OVF_CAP)
            g_ovf[slot] = make_int4(d, s << 8, __float_as_int(w), 0);
    }
}

__device__ __forceinline__ void scatter_quad(const int4& s4, const int4& d4,
                                             const float4& w4) {
    scatter_one(d4.x, s4.x, w4.x);
    scatter_one(d4.y, s4.y, w4.y);
    scatter_one(d4.z, s4.z, w4.z);
    scatter_one(d4.w, s4.w, w4.w);
}

__global__ __launch_bounds__(256)
void scatter_kernel(const int*   __restrict__ src,
                    const int*   __restrict__ dst,
                    const float* __restrict__ ew,
                    int E) {
    int t  = blockIdx.x * blockDim.x + threadIdx.x;
    int i0 = t * 8;
    if (i0 + 7 < E) {
        int4   sa = __ldg((const int4*)(src + i0));
        int4   sb = __ldg((const int4*)(src + i0) + 1);
        int4   da = __ldg((const int4*)(dst + i0));
        int4   db = __ldg((const int4*)(dst + i0) + 1);
        float4 wa = __ldg((const float4*)(ew + i0));
        float4 wb = __ldg((const float4*)(ew + i0) + 1);
        scatter_quad(sa, da, wa);
        scatter_quad(sb, db, wb);
    } else {
        for (int i = i0; i < E; i++)
            scatter_one(__ldg(dst + i), __ldg(src + i), __ldg(ew + i));
    }
}

// ---------------------------------------------------------------------------
// GEMM: Y = H * W'  (single-term fp16 tensor-core, fp32 accumulate).
// 128x128 tile/CTA, 256 threads / 8 warps (warp = 32m x 64n).
// Single staging phase: ALL of A (128x128) + W' (128x128) staged up front
// (MLP ~24 vector loads/thread), ONE sync, then 8 uninterrupted k-steps.
// ---------------------------------------------------------------------------
#define LDH  136    // fp16 leading dim for A and W panels (128 + 8 pad)
#define LDWF 136    // fp32 epilogue tile leading dim

#define A_OFF 0
#define W_OFF (BROWS * LDH)               // 17408 halves
// pool: 2 * 128 * 136 * 2 B = 69632 B; epilogue fp32 tile 128*136*4 = 69632 B

__global__ __launch_bounds__(256, 2)
void gemm_kernel(const float* __restrict__ H, int N) {
    extern __shared__ float smf[];
    __half* smh = (__half*)smf;

    int tid  = threadIdx.x;
    int row0 = blockIdx.x * BROWS;
    int wid  = tid >> 5;
    int m0   = (wid >> 1) * 32;
    int n0   = (wid & 1) * 64;

    // Stage ALL of A: 128 rows x 128 k, 16 float4/thread (independent loads).
    #pragma unroll
    for (int t = 0; t < 16; t++) {
        int i  = tid + t * 256;              // 0..4095
        int r  = i >> 5;                     // row 0..127 (32 float4/row)
        int c4 = i & 31;
        int gr = row0 + r;
        float4 v = make_float4(0.f, 0.f, 0.f, 0.f);
        if (gr < N) v = __ldg((const float4*)(H + (size_t)gr * D) + c4);
        __half2 p0 = __float22half2_rn(make_float2(v.x, v.y));
        __half2 p1 = __float22half2_rn(make_float2(v.z, v.w));
        int o = r * LDH + c4 * 4;
        *(__half2*)(smh + A_OFF + o)     = p0;
        *(__half2*)(smh + A_OFF + o + 2) = p1;
    }

    // Stage ALL of W': 128 k x 128 n, 8 uint4/thread (pure copies).
    #pragma unroll
    for (int t = 0; t < 8; t++) {
        int i  = tid + t * 256;              // 0..2047
        int k  = i >> 4;                     // 0..127 (16 uint4/row)
        int c8 = i & 15;
        uint4 vh = __ldg((const uint4*)(g_Wh + k * D) + c8);
        *(uint4*)(smh + W_OFF + k * LDH + c8 * 8) = vh;
    }
    __syncthreads();

    wmma::fragment<wmma::accumulator, 16, 16, 16, float> acc[2][4];
    #pragma unroll
    for (int mf = 0; mf < 2; mf++)
        #pragma unroll
        for (int nf = 0; nf < 4; nf++) wmma::fill_fragment(acc[mf][nf], 0.0f);

    #pragma unroll
    for (int kk = 0; kk < 8; kk++) {
        wmma::fragment<wmma::matrix_a, 16, 16, 16, __half, wmma::row_major> a[2];
        #pragma unroll
        for (int mf = 0; mf < 2; mf++)
            wmma::load_matrix_sync(a[mf], smh + A_OFF + (m0 + mf * 16) * LDH + kk * 16, LDH);
        #pragma unroll
        for (int nf = 0; nf < 4; nf++) {
            wmma::fragment<wmma::matrix_b, 16, 16, 16, __half, wmma::row_major> b;
            wmma::load_matrix_sync(b, smh + W_OFF + kk * 16 * LDH + n0 + nf * 16, LDH);
            #pragma unroll
            for (int mf = 0; mf < 2; mf++)
                wmma::mma_sync(acc[mf][nf], a[mf], b, acc[mf][nf]);
        }
    }
    __syncthreads();   // staging pool about to be overwritten by epilogue

    // Epilogue: dump accs to fp32 smem tile, convert to fp16 Y, store.
    #pragma unroll
    for (int mf = 0; mf < 2; mf++)
        #pragma unroll
        for (int nf = 0; nf < 4; nf++)
            wmma::store_matrix_sync(smf + (m0 + mf * 16) * LDWF + n0 + nf * 16,
                                    acc[mf][nf], LDWF, wmma::mem_row_major);
    __syncthreads();

    #pragma unroll
    for (int t = 0; t < 16; t++) {
        int i  = tid + t * 256;              // 0..4095  (128 rows x 32 groups)
        int r  = i >> 5;
        int c4 = i & 31;
        int gr = row0 + r;
        if (gr >= N) continue;
        const float* s = smf + r * LDWF + c4 * 4;
        __half2 p0 = __float22half2_rn(make_float2(s[0], s[1]));
        __half2 p1 = __float22half2_rn(make_float2(s[2], s[3]));
        uint2 u;
        u.x = *(unsigned int*)&p0;
        u.y = *(unsigned int*)&p1;
        *((uint2*)(g_Y + (size_t)gr * D) + c4) = u;
    }
}

// ---------------------------------------------------------------------------
// Gather: one warp per node; lane owns 4 columns.  8-edge unroll (MLP~8).
// ---------------------------------------------------------------------------
__device__ __forceinline__ float gelu_exact(float x) {
    return 0.5f * x * (1.0f + erff(x * 0.70710678118654752f));
}

__device__ __forceinline__ void fmaacc(float4& a, uint2 u, float w) {
    float2 f01 = __half22float2(*(const __half2*)&u.x);
    float2 f23 = __half22float2(*(const __half2*)&u.y);
    a.x += w * f01.x; a.y += w * f01.y;
    a.z += w * f23.x; a.w += w * f23.y;
}

__global__ __launch_bounds__(256)
void gather_kernel(float* __restrict__ out, int N) {
    int warp = (int)((blockIdx.x * (unsigned)blockDim.x + threadIdx.x) >> 5);
    int lane = threadIdx.x & 31;
    if (warp >= N) return;

    int cnt = g_cnt[warp];
    int deg = cnt < CAP ? cnt : CAP;
    const int4* lst4 = g_edge4 + (size_t)warp * (CAP / 2);

    float4 acc = make_float4(0.f, 0.f, 0.f, 0.f);

    int e = 0;
    for (; e + 8 <= deg; e += 8) {
        int4 m0 = __ldg(lst4 + (e >> 1));
        int4 m1 = __ldg(lst4 + (e >> 1) + 1);
        int4 m2 = __ldg(lst4 + (e >> 1) + 2);
        int4 m3 = __ldg(lst4 + (e >> 1) + 3);
        uint2 u0 = __ldg((const uint2*)((const char*)g_Y + m0.x) + lane);
        uint2 u1 = __ldg((const uint2*)((const char*)g_Y + m0.z) + lane);
        uint2 u2 = __ldg((const uint2*)((const char*)g_Y + m1.x) + lane);
        uint2 u3 = __ldg((const uint2*)((const char*)g_Y + m1.z) + lane);
        uint2 u4 = __ldg((const uint2*)((const char*)g_Y + m2.x) + lane);
        uint2 u5 = __ldg((const uint2*)((const char*)g_Y + m2.z) + lane);
        uint2 u6 = __ldg((const uint2*)((const char*)g_Y + m3.x) + lane);
        uint2 u7 = __ldg((const uint2*)((const char*)g_Y + m3.z) + lane);
        fmaacc(acc, u0, __int_as_float(m0.y));
        fmaacc(acc, u1, __int_as_float(m0.w));
        fmaacc(acc, u2, __int_as_float(m1.y));
        fmaacc(acc, u3, __int_as_float(m1.w));
        fmaacc(acc, u4, __int_as_float(m2.y));
        fmaacc(acc, u5, __int_as_float(m2.w));
        fmaacc(acc, u6, __int_as_float(m3.y));
        fmaacc(acc, u7, __int_as_float(m3.w));
    }
    for (; e < deg; e++) {
        int2 p = __ldg((const int2*)lst4 + e);
        uint2 u = __ldg((const uint2*)((const char*)g_Y + p.x) + lane);
        fmaacc(acc, u, __int_as_float(p.y));
    }

    if (cnt > CAP) {   // merge rare overflow entries (Y complete by now)
        int m = g_ovf_cnt;
        if (m > OVF_CAP) m = OVF_CAP;
        for (int i = 0; i < m; i++) {
            int4 o = g_ovf[i];
            if (o.x == warp) {
                uint2 u = __ldg((const uint2*)((const char*)g_Y + o.y) + lane);
                fmaacc(acc, u, __int_as_float(o.z));
            }
        }
    }

    float4 c4 = __ldg((const float4*)g_c + lane);
    float4 o;
    o.x = gelu_exact(acc.x + c4.x);
    o.y = gelu_exact(acc.y + c4.y);
    o.z = gelu_exact(acc.z + c4.z);
    o.w = gelu_exact(acc.w + c4.w);
    *((float4*)(out + (size_t)warp * D) + lane) = o;
}

// ---------------------------------------------------------------------------
extern "C" void kernel_launch(void* const* d_in, const int* in_sizes, int n_in,
                              void* d_out, int out_size) {
    const float* H     = (const float*)d_in[0];
    const int*   src   = (const int*)  d_in[1];
    const int*   dst   = (const int*)  d_in[2];
    const float* ew    = (const float*)d_in[3];
    const float* gamma = (const float*)d_in[4];
    const float* beta  = (const float*)d_in[5];
    const float* mean  = (const float*)d_in[6];
    const float* var   = (const float*)d_in[7];
    const float* W     = (const float*)d_in[8];
    const float* bias  = (const float*)d_in[9];

    int N = in_sizes[0] / D;
    int E = in_sizes[1];

    prep_all_kernel<<<456, 256>>>(W, bias, gamma, beta, mean, var, N);

    int sblocks = (E / 8 + 255) / 256 + 1;
    scatter_kernel<<<sblocks, 256>>>(src, dst, ew, E);

    int smem_bytes = BROWS * LDWF * 4;       // 69632 B
    cudaFuncSetAttribute(gemm_kernel,
                         cudaFuncAttributeMaxDynamicSharedMemorySize, smem_bytes);
    gemm_kernel<<<(N + BROWS - 1) / BROWS, 256, smem_bytes>>>(H, N);

    gather_kernel<<<(N * 32 + 255) / 256, 256>>>((float*)d_out, N);
}